// round 2
// baseline (speedup 1.0000x reference)
#include <cuda_runtime.h>
#include <mma.h>
#include <cstdint>

using namespace nvcuda;

// Problem constants (fixed by setup_inputs)
#define BATCH   16
#define SEQ     4096
#define TOKENS  (BATCH * SEQ)      // 65536
#define C_DIM   256
#define N_QKV   (3 * C_DIM)        // 768

// Scratch (allocation-free: __device__ globals)
__device__ float g_qkv[3ULL * TOKENS * N_QKV];     // [branch][token][768]
__device__ float g_comb[(size_t)TOKENS * C_DIM];   // [token][256]

__device__ __forceinline__ float to_tf32(float x) {
    unsigned r;
    asm("cvt.rna.tf32.f32 %0, %1;" : "=r"(r) : "f"(x));
    return __uint_as_float(r);
}

// ---------------------------------------------------------------------------
// tf32 WMMA GEMM:  C = A(MxK, row-major) * B(KxN, row-major)
// Block tile 128x128, K-tile 32. 8 warps (2x4), warp tile 64x32 (4x2 frags).
// Register-staged prefetch pipeline: next tile's LDGs issue before compute of
// the current tile; tf32 conversion happens ONCE per element at smem store.
// blockIdx.z selects a branch via bStrideZ / cStrideZ.
// ---------------------------------------------------------------------------
#define BM 128
#define BN 128
#define BK 32

__global__ __launch_bounds__(256) void gemm_tf32(
    const float* __restrict__ A, const float* __restrict__ B,
    float* __restrict__ Co, int M, int N, int K,
    size_t bStrideZ, size_t cStrideZ)
{
    __shared__ float As[BM][BK + 4];   // row stride 36 floats (16B aligned)
    __shared__ float Bs[BK][BN + 4];   // row stride 132 floats (16B aligned)

    const float* Bz = B + (size_t)blockIdx.z * bStrideZ;
    float*       Cz = Co + (size_t)blockIdx.z * cStrideZ;

    const int tileM = blockIdx.y;
    const int tileN = blockIdx.x;
    const int tid   = threadIdx.x;
    const int warp  = tid >> 5;
    const int wy    = warp >> 2;   // 0..1  (64 rows each)
    const int wx    = warp & 3;    // 0..3  (32 cols each)

    // Per-thread load coordinates (fixed across k-tiles)
    const int ar  = tid >> 3;          // A row within tile for p=0 (step 32 rows per p? no: idx-based)
    const int ac4 = tid & 7;
    const int br  = tid >> 5;
    const int bc4 = tid & 31;

    wmma::fragment<wmma::accumulator, 16, 16, 8, float> acc[4][2];
    #pragma unroll
    for (int i = 0; i < 4; i++)
        #pragma unroll
        for (int j = 0; j < 2; j++)
            wmma::fill_fragment(acc[i][j], 0.0f);

    const int nk = K / BK;
    float4 ra[4], rb[4];

    // Prologue: prefetch k-tile 0 into registers
    #pragma unroll
    for (int p = 0; p < 4; p++) {
        int r = ar + p * 32;
        ra[p] = *(const float4*)(A + (size_t)(tileM * BM + r) * K + 0 + ac4 * 4);
    }
    #pragma unroll
    for (int p = 0; p < 4; p++) {
        int r = br + p * 8;
        rb[p] = *(const float4*)(Bz + (size_t)(0 + r) * N + tileN * BN + bc4 * 4);
    }

    for (int kt = 0; kt < nk; kt++) {
        // Convert to tf32 and store staged registers to smem
        #pragma unroll
        for (int p = 0; p < 4; p++) {
            int r = ar + p * 32;
            float4 v = ra[p];
            v.x = to_tf32(v.x); v.y = to_tf32(v.y);
            v.z = to_tf32(v.z); v.w = to_tf32(v.w);
            *(float4*)(&As[r][ac4 * 4]) = v;
        }
        #pragma unroll
        for (int p = 0; p < 4; p++) {
            int r = br + p * 8;
            float4 v = rb[p];
            v.x = to_tf32(v.x); v.y = to_tf32(v.y);
            v.z = to_tf32(v.z); v.w = to_tf32(v.w);
            *(float4*)(&Bs[r][bc4 * 4]) = v;
        }
        __syncthreads();

        // Issue next tile's global loads (latency hidden behind compute)
        if (kt + 1 < nk) {
            int k0 = (kt + 1) * BK;
            #pragma unroll
            for (int p = 0; p < 4; p++) {
                int r = ar + p * 32;
                ra[p] = *(const float4*)(A + (size_t)(tileM * BM + r) * K + k0 + ac4 * 4);
            }
            #pragma unroll
            for (int p = 0; p < 4; p++) {
                int r = br + p * 8;
                rb[p] = *(const float4*)(Bz + (size_t)(k0 + r) * N + tileN * BN + bc4 * 4);
            }
        }

        // Compute this tile (values in smem are already tf32-rounded)
        #pragma unroll
        for (int ks = 0; ks < BK; ks += 8) {
            wmma::fragment<wmma::matrix_a, 16, 16, 8, wmma::precision::tf32, wmma::row_major> af[4];
            wmma::fragment<wmma::matrix_b, 16, 16, 8, wmma::precision::tf32, wmma::row_major> bf[2];
            #pragma unroll
            for (int i = 0; i < 4; i++)
                wmma::load_matrix_sync(af[i], &As[wy * 64 + i * 16][ks], BK + 4);
            #pragma unroll
            for (int j = 0; j < 2; j++)
                wmma::load_matrix_sync(bf[j], &Bs[ks][wx * 32 + j * 16], BN + 4);
            #pragma unroll
            for (int i = 0; i < 4; i++)
                #pragma unroll
                for (int j = 0; j < 2; j++)
                    wmma::mma_sync(acc[i][j], af[i], bf[j], acc[i][j]);
        }
        __syncthreads();
    }

    #pragma unroll
    for (int i = 0; i < 4; i++)
        #pragma unroll
        for (int j = 0; j < 2; j++) {
            int r0 = tileM * BM + wy * 64 + i * 16;
            int c0 = tileN * BN + wx * 32 + j * 16;
            wmma::store_matrix_sync(Cz + (size_t)r0 * N + c0, acc[i][j], N, wmma::mem_row_major);
        }
}

// ---------------------------------------------------------------------------
// Dilated local attention (K=3 taps, dilations 1,2,3), mean over 3 branches.
// One warp per token; lane owns 8 channels. Reads g_qkv, writes g_comb.
// Reference zero-pads: out-of-range taps contribute logit 0 and value 0.
// ---------------------------------------------------------------------------
__global__ __launch_bounds__(256) void attn_kernel()
{
    const int lane = threadIdx.x & 31;
    const int t    = blockIdx.x * 8 + (threadIdx.x >> 5);   // token
    const int n    = t & (SEQ - 1);                         // pos within batch
    const float scale = 0.0625f;                            // 256^-0.5

    float out[8];
    #pragma unroll
    for (int c = 0; c < 8; c++) out[c] = 0.0f;

    #pragma unroll
    for (int br = 0; br < 3; br++) {
        const int d = br + 1;
        const float* base = g_qkv + ((size_t)br * TOKENS + t) * N_QKV;

        float q[8];
        {
            float4 a = *(const float4*)(base + lane * 8);
            float4 b = *(const float4*)(base + lane * 8 + 4);
            q[0]=a.x; q[1]=a.y; q[2]=a.z; q[3]=a.w;
            q[4]=b.x; q[5]=b.y; q[6]=b.z; q[7]=b.w;
        }

        float lg[3];
        float vv[3][8];
        #pragma unroll
        for (int j = 0; j < 3; j++) {
            int off = (j - 1) * d;
            bool ok = ((unsigned)(n + off) < (unsigned)SEQ);
            float dot = 0.0f;
            if (ok) {
                const float* kr = base + (ptrdiff_t)off * N_QKV + C_DIM;
                float4 k0 = *(const float4*)(kr + lane * 8);
                float4 k1 = *(const float4*)(kr + lane * 8 + 4);
                dot = q[0]*k0.x + q[1]*k0.y + q[2]*k0.z + q[3]*k0.w
                    + q[4]*k1.x + q[5]*k1.y + q[6]*k1.z + q[7]*k1.w;
                const float* vr = base + (ptrdiff_t)off * N_QKV + 2 * C_DIM;
                float4 v0 = *(const float4*)(vr + lane * 8);
                float4 v1 = *(const float4*)(vr + lane * 8 + 4);
                vv[j][0]=v0.x; vv[j][1]=v0.y; vv[j][2]=v0.z; vv[j][3]=v0.w;
                vv[j][4]=v1.x; vv[j][5]=v1.y; vv[j][6]=v1.z; vv[j][7]=v1.w;
            } else {
                #pragma unroll
                for (int c = 0; c < 8; c++) vv[j][c] = 0.0f;
            }
            lg[j] = dot;   // 0 when out-of-range (zero-padded k row)
        }

        // Warp-reduce the three partial dot products
        #pragma unroll
        for (int s = 16; s > 0; s >>= 1) {
            lg[0] += __shfl_xor_sync(0xffffffffu, lg[0], s);
            lg[1] += __shfl_xor_sync(0xffffffffu, lg[1], s);
            lg[2] += __shfl_xor_sync(0xffffffffu, lg[2], s);
        }
        lg[0] *= scale; lg[1] *= scale; lg[2] *= scale;

        float m  = fmaxf(lg[0], fmaxf(lg[1], lg[2]));
        float e0 = expf(lg[0] - m);
        float e1 = expf(lg[1] - m);
        float e2 = expf(lg[2] - m);
        float inv = 1.0f / (e0 + e1 + e2);
        float a0 = e0 * inv, a1 = e1 * inv, a2 = e2 * inv;

        #pragma unroll
        for (int c = 0; c < 8; c++)
            out[c] += a0 * vv[0][c] + a1 * vv[1][c] + a2 * vv[2][c];
    }

    const float third = 1.0f / 3.0f;
    float4 o0, o1;
    o0.x = out[0]*third; o0.y = out[1]*third; o0.z = out[2]*third; o0.w = out[3]*third;
    o1.x = out[4]*third; o1.y = out[5]*third; o1.z = out[6]*third; o1.w = out[7]*third;
    float* dst = g_comb + (size_t)t * C_DIM + lane * 8;
    *(float4*)(dst)     = o0;
    *(float4*)(dst + 4) = o1;
}

// ---------------------------------------------------------------------------
// Bias add (vectorized): out[m][c] += bproj[c]
// ---------------------------------------------------------------------------
__global__ __launch_bounds__(256) void bias_add(float4* __restrict__ out,
                                                const float4* __restrict__ b,
                                                size_t total4)
{
    size_t i = (size_t)blockIdx.x * blockDim.x + threadIdx.x;
    size_t stride = (size_t)gridDim.x * blockDim.x;
    for (; i < total4; i += stride) {
        float4 v = out[i];
        float4 bb = b[i & (C_DIM / 4 - 1)];
        v.x += bb.x; v.y += bb.y; v.z += bb.z; v.w += bb.w;
        out[i] = v;
    }
}

// ---------------------------------------------------------------------------
// kernel_launch
// Inputs: d_in[0]=x (16,4096,256) f32, d_in[1]=Wqkv (3,256,768) f32,
//         d_in[2]=Wproj (256,256) f32, d_in[3]=bproj (256,) f32
// Output: (16,4096,256) f32
// ---------------------------------------------------------------------------
extern "C" void kernel_launch(void* const* d_in, const int* in_sizes, int n_in,
                              void* d_out, int out_size)
{
    const float* x     = (const float*)d_in[0];
    const float* Wqkv  = (const float*)d_in[1];
    const float* Wproj = (const float*)d_in[2];
    const float* bproj = (const float*)d_in[3];
    float*       out   = (float*)d_out;

    float* qkv  = nullptr;
    float* comb = nullptr;
    cudaGetSymbolAddress((void**)&qkv,  g_qkv);
    cudaGetSymbolAddress((void**)&comb, g_comb);

    // 1) QKV GEMM: 3 branches of (65536x256) @ (256x768)
    {
        dim3 grid(N_QKV / BN, TOKENS / BM, 3);
        gemm_tf32<<<grid, 256>>>(x, Wqkv, qkv, TOKENS, N_QKV, C_DIM,
                                 (size_t)C_DIM * N_QKV,
                                 (size_t)TOKENS * N_QKV);
    }

    // 2) Fused dilated local attention + mean over branches
    attn_kernel<<<TOKENS / 8, 256>>>();

    // 3) Proj GEMM: (65536x256) @ (256x256) -> out
    {
        dim3 grid(C_DIM / BN, TOKENS / BM, 1);
        gemm_tf32<<<grid, 256>>>(comb, Wproj, out, TOKENS, C_DIM, C_DIM, 0, 0);
    }

    // 4) Bias add
    bias_add<<<2048, 256>>>((float4*)out, (const float4*)bproj,
                            (size_t)TOKENS * C_DIM / 4);
}

// round 7
// speedup vs baseline: 1.8811x; 1.8811x over previous
#include <cuda_runtime.h>
#include <mma.h>
#include <cstdint>

using namespace nvcuda;

// Problem constants (fixed by setup_inputs)
#define BATCH   16
#define SEQ     4096
#define TOKENS  (BATCH * SEQ)      // 65536
#define C_DIM   256
#define N_QKV   (3 * C_DIM)        // 768

// Scratch (allocation-free: __device__ globals)
__device__ float g_qkv[3ULL * TOKENS * N_QKV];      // [branch][token][768]
__device__ float g_comb[(size_t)TOKENS * C_DIM];    // [token][256] (tf32-rounded)
__device__ float g_x32[(size_t)TOKENS * C_DIM];     // x rounded to tf32
__device__ float g_wq32[3ULL * C_DIM * N_QKV];      // Wqkv rounded to tf32
__device__ float g_wp32[(size_t)C_DIM * C_DIM];     // Wproj rounded to tf32

__device__ __forceinline__ float to_tf32(float x) {
    unsigned r;
    asm("cvt.rna.tf32.f32 %0, %1;" : "=r"(r) : "f"(x));
    return __uint_as_float(r);
}

// ---------------------------------------------------------------------------
// cp.async helpers
// ---------------------------------------------------------------------------
__device__ __forceinline__ void cp_async16(float* smem_dst, const float* gsrc) {
    uint32_t s = (uint32_t)__cvta_generic_to_shared(smem_dst);
    asm volatile("cp.async.cg.shared.global [%0], [%1], 16;\n" :: "r"(s), "l"(gsrc));
}
__device__ __forceinline__ void cp_commit() {
    asm volatile("cp.async.commit_group;\n");
}
__device__ __forceinline__ void cp_wait0() {
    asm volatile("cp.async.wait_group 0;\n");
}

// ---------------------------------------------------------------------------
// Elementwise tf32 rounding pass (float4 vectorized)
// ---------------------------------------------------------------------------
__global__ __launch_bounds__(256) void round_tf32(const float4* __restrict__ in,
                                                  float4* __restrict__ out,
                                                  size_t n4)
{
    size_t i = (size_t)blockIdx.x * blockDim.x + threadIdx.x;
    size_t stride = (size_t)gridDim.x * blockDim.x;
    for (; i < n4; i += stride) {
        float4 v = in[i];
        v.x = to_tf32(v.x); v.y = to_tf32(v.y);
        v.z = to_tf32(v.z); v.w = to_tf32(v.w);
        out[i] = v;
    }
}

// ---------------------------------------------------------------------------
// tf32 WMMA GEMM, cp.async double-buffered:
//   C = A(MxK row-major, already tf32-rounded) * B(KxN row-major, tf32-rounded)
// Block tile 128x128, BK=32, 256 threads (8 warps 2x4, warp tile 64x32).
// If bias != nullptr, epilogue adds bias[col] (smem-staged store).
// blockIdx.z selects branch via bStrideZ/cStrideZ.
// ---------------------------------------------------------------------------
#define BM 128
#define BN 128
#define BK 32

#define A_STRIDE 36   // floats per A smem row (16B-aligned padding)
#define B_STRIDE 132  // floats per B smem row
#define A_STAGE  (BM * A_STRIDE)   // 4608 floats
#define B_STAGE  (BK * B_STRIDE)   // 4224 floats
#define SMEM_FLOATS (2 * A_STAGE + 2 * B_STAGE)   // 17664 floats = 70656 B

__global__ __launch_bounds__(256, 2) void gemm_tf32_async(
    const float* __restrict__ A, const float* __restrict__ B,
    float* __restrict__ Co, int M, int N, int K,
    size_t bStrideZ, size_t cStrideZ,
    const float* __restrict__ bias)
{
    extern __shared__ float smem[];
    float* As0 = smem;
    float* As1 = smem + A_STAGE;
    float* Bs0 = smem + 2 * A_STAGE;
    float* Bs1 = smem + 2 * A_STAGE + B_STAGE;

    const float* Bz = B + (size_t)blockIdx.z * bStrideZ;
    float*       Cz = Co + (size_t)blockIdx.z * cStrideZ;

    const int tileM = blockIdx.y;
    const int tileN = blockIdx.x;
    const int tid   = threadIdx.x;
    const int warp  = tid >> 5;
    const int lane  = tid & 31;
    const int wy    = warp >> 2;   // 0..1
    const int wx    = warp & 3;    // 0..3

    const int ar  = tid >> 3;      // A row (p adds 32)
    const int ac4 = tid & 7;       // A float4 col
    const int br  = tid >> 5;      // B row (p adds 8)
    const int bc4 = tid & 31;      // B float4 col

    const float* Ag = A + (size_t)(tileM * BM + ar) * K + ac4 * 4;
    const float* Bg = Bz + (size_t)br * N + tileN * BN + bc4 * 4;

    wmma::fragment<wmma::accumulator, 16, 16, 8, float> acc[4][2];
    #pragma unroll
    for (int i = 0; i < 4; i++)
        #pragma unroll
        for (int j = 0; j < 2; j++)
            wmma::fill_fragment(acc[i][j], 0.0f);

    const int nk = K / BK;   // 8 for K=256

    // Prologue: stage 0
    #pragma unroll
    for (int p = 0; p < 4; p++)
        cp_async16(As0 + (ar + p * 32) * A_STRIDE + ac4 * 4, Ag + (size_t)(p * 32) * K);
    #pragma unroll
    for (int p = 0; p < 4; p++)
        cp_async16(Bs0 + (br + p * 8) * B_STRIDE + bc4 * 4, Bg + (size_t)(p * 8) * N);
    cp_commit();
    cp_wait0();
    __syncthreads();

    for (int kt = 0; kt < nk; kt++) {
        float* Ac = (kt & 1) ? As1 : As0;
        float* Bc = (kt & 1) ? Bs1 : Bs0;
        float* An = (kt & 1) ? As0 : As1;
        float* Bn = (kt & 1) ? Bs0 : Bs1;

        if (kt + 1 < nk) {
            int k0 = (kt + 1) * BK;
            #pragma unroll
            for (int p = 0; p < 4; p++)
                cp_async16(An + (ar + p * 32) * A_STRIDE + ac4 * 4,
                           Ag + k0 + (size_t)(p * 32) * K);
            #pragma unroll
            for (int p = 0; p < 4; p++)
                cp_async16(Bn + (br + p * 8) * B_STRIDE + bc4 * 4,
                           Bg + (size_t)(k0 + p * 8) * N);
            cp_commit();
        }

        #pragma unroll
        for (int ks = 0; ks < BK; ks += 8) {
            wmma::fragment<wmma::matrix_a, 16, 16, 8, wmma::precision::tf32, wmma::row_major> af[4];
            wmma::fragment<wmma::matrix_b, 16, 16, 8, wmma::precision::tf32, wmma::row_major> bf[2];
            #pragma unroll
            for (int i = 0; i < 4; i++)
                wmma::load_matrix_sync(af[i], Ac + (wy * 64 + i * 16) * A_STRIDE + ks, A_STRIDE);
            #pragma unroll
            for (int j = 0; j < 2; j++)
                wmma::load_matrix_sync(bf[j], Bc + ks * B_STRIDE + wx * 32 + j * 16, B_STRIDE);
            #pragma unroll
            for (int i = 0; i < 4; i++)
                #pragma unroll
                for (int j = 0; j < 2; j++)
                    wmma::mma_sync(acc[i][j], af[i], bf[j], acc[i][j]);
        }

        if (kt + 1 < nk) cp_wait0();
        __syncthreads();
    }

    if (bias == nullptr) {
        // Direct store
        #pragma unroll
        for (int i = 0; i < 4; i++)
            #pragma unroll
            for (int j = 0; j < 2; j++) {
                int r0 = tileM * BM + wy * 64 + i * 16;
                int c0 = tileN * BN + wx * 32 + j * 16;
                wmma::store_matrix_sync(Cz + (size_t)r0 * N + c0, acc[i][j], N,
                                        wmma::mem_row_major);
            }
    } else {
        // Smem-staged store with bias add (reuse pipeline smem; all warps done
        // with their own reads after the final syncthreads above)
        float* epi = smem + warp * 256;
        const int er = lane >> 1;            // row 0..15
        const int ec = (lane & 1) * 8;       // col 0 or 8
        #pragma unroll
        for (int i = 0; i < 4; i++)
            #pragma unroll
            for (int j = 0; j < 2; j++) {
                wmma::store_matrix_sync(epi, acc[i][j], 16, wmma::mem_row_major);
                __syncwarp();
                int gr = tileM * BM + wy * 64 + i * 16 + er;
                int gc = tileN * BN + wx * 32 + j * 16 + ec;
                float4 v0 = *(float4*)(epi + er * 16 + ec);
                float4 v1 = *(float4*)(epi + er * 16 + ec + 4);
                float4 b0 = __ldg((const float4*)(bias + gc));
                float4 b1 = __ldg((const float4*)(bias + gc + 4));
                v0.x += b0.x; v0.y += b0.y; v0.z += b0.z; v0.w += b0.w;
                v1.x += b1.x; v1.y += b1.y; v1.z += b1.z; v1.w += b1.w;
                *(float4*)(Cz + (size_t)gr * N + gc)     = v0;
                *(float4*)(Cz + (size_t)gr * N + gc + 4) = v1;
                __syncwarp();
            }
    }
}

// ---------------------------------------------------------------------------
// Dilated local attention (K=3 taps, dilations 1,2,3), mean over 3 branches.
// One warp per token; lane owns 8 channels. Reads g_qkv, writes g_comb
// (tf32-rounded so the proj GEMM needs no conversion).
// Reference zero-pads: out-of-range taps contribute logit 0 and value 0.
// ---------------------------------------------------------------------------
__global__ __launch_bounds__(256) void attn_kernel()
{
    const int lane = threadIdx.x & 31;
    const int t    = blockIdx.x * 8 + (threadIdx.x >> 5);   // token
    const int n    = t & (SEQ - 1);                         // pos within batch
    const float scale = 0.0625f;                            // 256^-0.5

    float out[8];
    #pragma unroll
    for (int c = 0; c < 8; c++) out[c] = 0.0f;

    #pragma unroll
    for (int br = 0; br < 3; br++) {
        const int d = br + 1;
        const float* base = g_qkv + ((size_t)br * TOKENS + t) * N_QKV;

        float q[8];
        {
            float4 a = *(const float4*)(base + lane * 8);
            float4 b = *(const float4*)(base + lane * 8 + 4);
            q[0]=a.x; q[1]=a.y; q[2]=a.z; q[3]=a.w;
            q[4]=b.x; q[5]=b.y; q[6]=b.z; q[7]=b.w;
        }

        float lg[3];
        float vv[3][8];
        #pragma unroll
        for (int j = 0; j < 3; j++) {
            int off = (j - 1) * d;
            bool ok = ((unsigned)(n + off) < (unsigned)SEQ);
            float dot = 0.0f;
            if (ok) {
                const float* kr = base + (ptrdiff_t)off * N_QKV + C_DIM;
                float4 k0 = *(const float4*)(kr + lane * 8);
                float4 k1 = *(const float4*)(kr + lane * 8 + 4);
                dot = q[0]*k0.x + q[1]*k0.y + q[2]*k0.z + q[3]*k0.w
                    + q[4]*k1.x + q[5]*k1.y + q[6]*k1.z + q[7]*k1.w;
                const float* vr = base + (ptrdiff_t)off * N_QKV + 2 * C_DIM;
                float4 v0 = *(const float4*)(vr + lane * 8);
                float4 v1 = *(const float4*)(vr + lane * 8 + 4);
                vv[j][0]=v0.x; vv[j][1]=v0.y; vv[j][2]=v0.z; vv[j][3]=v0.w;
                vv[j][4]=v1.x; vv[j][5]=v1.y; vv[j][6]=v1.z; vv[j][7]=v1.w;
            } else {
                #pragma unroll
                for (int c = 0; c < 8; c++) vv[j][c] = 0.0f;
            }
            lg[j] = dot;   // 0 when out-of-range (zero-padded k row)
        }

        // Warp-reduce the three partial dot products
        #pragma unroll
        for (int s = 16; s > 0; s >>= 1) {
            lg[0] += __shfl_xor_sync(0xffffffffu, lg[0], s);
            lg[1] += __shfl_xor_sync(0xffffffffu, lg[1], s);
            lg[2] += __shfl_xor_sync(0xffffffffu, lg[2], s);
        }
        lg[0] *= scale; lg[1] *= scale; lg[2] *= scale;

        float m  = fmaxf(lg[0], fmaxf(lg[1], lg[2]));
        float e0 = expf(lg[0] - m);
        float e1 = expf(lg[1] - m);
        float e2 = expf(lg[2] - m);
        float inv = 1.0f / (e0 + e1 + e2);
        float a0 = e0 * inv, a1 = e1 * inv, a2 = e2 * inv;

        #pragma unroll
        for (int c = 0; c < 8; c++)
            out[c] += a0 * vv[0][c] + a1 * vv[1][c] + a2 * vv[2][c];
    }

    const float third = 1.0f / 3.0f;
    float4 o0, o1;
    o0.x = to_tf32(out[0]*third); o0.y = to_tf32(out[1]*third);
    o0.z = to_tf32(out[2]*third); o0.w = to_tf32(out[3]*third);
    o1.x = to_tf32(out[4]*third); o1.y = to_tf32(out[5]*third);
    o1.z = to_tf32(out[6]*third); o1.w = to_tf32(out[7]*third);
    float* dst = g_comb + (size_t)t * C_DIM + lane * 8;
    *(float4*)(dst)     = o0;
    *(float4*)(dst + 4) = o1;
}

// ---------------------------------------------------------------------------
// kernel_launch
// Inputs: d_in[0]=x (16,4096,256) f32, d_in[1]=Wqkv (3,256,768) f32,
//         d_in[2]=Wproj (256,256) f32, d_in[3]=bproj (256,) f32
// Output: (16,4096,256) f32
// ---------------------------------------------------------------------------
extern "C" void kernel_launch(void* const* d_in, const int* in_sizes, int n_in,
                              void* d_out, int out_size)
{
    const float* x     = (const float*)d_in[0];
    const float* Wqkv  = (const float*)d_in[1];
    const float* Wproj = (const float*)d_in[2];
    const float* bproj = (const float*)d_in[3];
    float*       out   = (float*)d_out;

    float *qkv, *comb, *x32, *wq32, *wp32;
    cudaGetSymbolAddress((void**)&qkv,  g_qkv);
    cudaGetSymbolAddress((void**)&comb, g_comb);
    cudaGetSymbolAddress((void**)&x32,  g_x32);
    cudaGetSymbolAddress((void**)&wq32, g_wq32);
    cudaGetSymbolAddress((void**)&wp32, g_wp32);

    static bool attr_done = false;
    if (!attr_done) {
        cudaFuncSetAttribute(gemm_tf32_async,
                             cudaFuncAttributeMaxDynamicSharedMemorySize,
                             SMEM_FLOATS * sizeof(float));
        attr_done = true;
    }

    // 0) Round inputs to tf32 once
    round_tf32<<<2048, 256>>>((const float4*)x, (float4*)x32,
                              (size_t)TOKENS * C_DIM / 4);
    round_tf32<<<144, 256>>>((const float4*)Wqkv, (float4*)wq32,
                             (size_t)3 * C_DIM * N_QKV / 4);
    round_tf32<<<16, 256>>>((const float4*)Wproj, (float4*)wp32,
                            (size_t)C_DIM * C_DIM / 4);

    // 1) QKV GEMM: 3 branches of (65536x256) @ (256x768)
    {
        dim3 grid(N_QKV / BN, TOKENS / BM, 3);
        gemm_tf32_async<<<grid, 256, SMEM_FLOATS * sizeof(float)>>>(
            x32, wq32, qkv, TOKENS, N_QKV, C_DIM,
            (size_t)C_DIM * N_QKV, (size_t)TOKENS * N_QKV, nullptr);
    }

    // 2) Fused dilated local attention + mean over branches
    attn_kernel<<<TOKENS / 8, 256>>>();

    // 3) Proj GEMM with fused bias: (65536x256) @ (256x256) + b -> out
    {
        dim3 grid(C_DIM / BN, TOKENS / BM, 1);
        gemm_tf32_async<<<grid, 256, SMEM_FLOATS * sizeof(float)>>>(
            comb, wp32, out, TOKENS, C_DIM, C_DIM, 0, 0, bproj);
    }
}

// round 8
// speedup vs baseline: 1.8955x; 1.0077x over previous
#include <cuda_runtime.h>
#include <mma.h>
#include <cstdint>

using namespace nvcuda;

// Problem constants (fixed by setup_inputs)
#define BATCH   16
#define SEQ     4096
#define TOKENS  (BATCH * SEQ)      // 65536
#define C_DIM   256
#define N_QKV   768                // per-branch qkv width
#define N_ALL   2304               // 3 branches merged along N

// Scratch (allocation-free: __device__ globals)
__device__ float g_qkv[(size_t)TOKENS * N_ALL];     // [token][br*768 + {q,k,v}]
__device__ float g_comb[(size_t)TOKENS * C_DIM];    // [token][256] (tf32-rounded)
__device__ float g_x32[(size_t)TOKENS * C_DIM];     // x rounded to tf32
__device__ float g_wq32[(size_t)C_DIM * N_ALL];     // Wqkv repacked+rounded: [k][br*768+n]
__device__ float g_wp32[(size_t)C_DIM * C_DIM];     // Wproj rounded to tf32

__device__ __forceinline__ float to_tf32(float x) {
    unsigned r;
    asm("cvt.rna.tf32.f32 %0, %1;" : "=r"(r) : "f"(x));
    return __uint_as_float(r);
}

// ---------------------------------------------------------------------------
// cp.async helpers
// ---------------------------------------------------------------------------
__device__ __forceinline__ void cp_async16(float* smem_dst, const float* gsrc) {
    uint32_t s = (uint32_t)__cvta_generic_to_shared(smem_dst);
    asm volatile("cp.async.cg.shared.global [%0], [%1], 16;\n" :: "r"(s), "l"(gsrc));
}
__device__ __forceinline__ void cp_commit() {
    asm volatile("cp.async.commit_group;\n");
}
template <int NN>
__device__ __forceinline__ void cp_wait() {
    asm volatile("cp.async.wait_group %0;\n" :: "n"(NN));
}

// ---------------------------------------------------------------------------
// Elementwise tf32 rounding pass (float4 vectorized)
// ---------------------------------------------------------------------------
__global__ __launch_bounds__(256) void round_tf32(const float4* __restrict__ in,
                                                  float4* __restrict__ out,
                                                  size_t n4)
{
    size_t i = (size_t)blockIdx.x * blockDim.x + threadIdx.x;
    size_t stride = (size_t)gridDim.x * blockDim.x;
    for (; i < n4; i += stride) {
        float4 v = in[i];
        v.x = to_tf32(v.x); v.y = to_tf32(v.y);
        v.z = to_tf32(v.z); v.w = to_tf32(v.w);
        out[i] = v;
    }
}

// ---------------------------------------------------------------------------
// Repack Wqkv [3][256][768] -> [256][2304] (branch-major within row), tf32.
// float4 over n; total 3*256*192 = 147456 float4s.
// ---------------------------------------------------------------------------
__global__ __launch_bounds__(256) void repack_wqkv(const float4* __restrict__ in,
                                                   float4* __restrict__ out)
{
    int idx = blockIdx.x * 256 + threadIdx.x;     // < 147456
    const int n4 = N_QKV / 4;                     // 192
    int br  = idx / (C_DIM * n4);
    int rem = idx % (C_DIM * n4);
    int k   = rem / n4;
    int c4  = rem % n4;
    float4 v = in[idx];
    v.x = to_tf32(v.x); v.y = to_tf32(v.y);
    v.z = to_tf32(v.z); v.w = to_tf32(v.w);
    out[(size_t)k * (N_ALL / 4) + br * n4 + c4] = v;
}

// ---------------------------------------------------------------------------
// tf32 WMMA GEMM, 3-stage cp.async pipeline:
//   C = A(MxK row-major, tf32-rounded) * B(KxN row-major, tf32-rounded)
// Block tile 128x128, BK=32, 256 threads (8 warps 2x4, warp tile 64x32).
// If bias != nullptr, epilogue adds bias[col] (smem-staged store).
// ---------------------------------------------------------------------------
#define BM 128
#define BN 128
#define BK 32

#define A_STRIDE 36                   // floats per A smem row
#define B_STRIDE 132                  // floats per B smem row
#define A_STAGE  (BM * A_STRIDE)      // 4608 floats
#define B_STAGE  (BK * B_STRIDE)      // 4224 floats
#define STAGE_FLOATS (A_STAGE + B_STAGE)          // 8832 floats = 35328 B
#define NSTAGE 3
#define SMEM_FLOATS (NSTAGE * STAGE_FLOATS)       // 26496 floats = 105984 B

__global__ __launch_bounds__(256, 2) void gemm_tf32_async(
    const float* __restrict__ A, const float* __restrict__ B,
    float* __restrict__ Co, int M, int N, int K,
    const float* __restrict__ bias)
{
    extern __shared__ float smem[];

    const int tileM = blockIdx.y;
    const int tileN = blockIdx.x;
    const int tid   = threadIdx.x;
    const int warp  = tid >> 5;
    const int lane  = tid & 31;
    const int wy    = warp >> 2;   // 0..1
    const int wx    = warp & 3;    // 0..3

    const int ar  = tid >> 3;      // A row (p adds 32)
    const int ac4 = tid & 7;       // A float4 col
    const int br  = tid >> 5;      // B row (p adds 8)
    const int bc4 = tid & 31;      // B float4 col

    const float* Ag = A + (size_t)(tileM * BM + ar) * K + ac4 * 4;
    const float* Bg = B + (size_t)br * N + tileN * BN + bc4 * 4;

    wmma::fragment<wmma::accumulator, 16, 16, 8, float> acc[4][2];
    #pragma unroll
    for (int i = 0; i < 4; i++)
        #pragma unroll
        for (int j = 0; j < 2; j++)
            wmma::fill_fragment(acc[i][j], 0.0f);

    const int nk = K / BK;   // 8 for K=256

    // Prologue: prefetch stages 0 and 1 (one commit group each)
    #pragma unroll
    for (int s = 0; s < 2; s++) {
        float* As = smem + s * STAGE_FLOATS;
        float* Bs = As + A_STAGE;
        int k0 = s * BK;
        #pragma unroll
        for (int p = 0; p < 4; p++)
            cp_async16(As + (ar + p * 32) * A_STRIDE + ac4 * 4,
                       Ag + k0 + (size_t)(p * 32) * K);
        #pragma unroll
        for (int p = 0; p < 4; p++)
            cp_async16(Bs + (br + p * 8) * B_STRIDE + bc4 * 4,
                       Bg + (size_t)(k0 + p * 8) * N);
        cp_commit();
    }

    for (int kt = 0; kt < nk; kt++) {
        // Ensure stage kt is resident (leave at most one group in flight)
        if (kt + 1 < nk) cp_wait<1>(); else cp_wait<0>();
        __syncthreads();   // all warps done reading stage (kt+2)%3 (iter kt-1)

        // Prefetch stage kt+2
        if (kt + 2 < nk) {
            float* An = smem + ((kt + 2) % NSTAGE) * STAGE_FLOATS;
            float* Bn = An + A_STAGE;
            int k0 = (kt + 2) * BK;
            #pragma unroll
            for (int p = 0; p < 4; p++)
                cp_async16(An + (ar + p * 32) * A_STRIDE + ac4 * 4,
                           Ag + k0 + (size_t)(p * 32) * K);
            #pragma unroll
            for (int p = 0; p < 4; p++)
                cp_async16(Bn + (br + p * 8) * B_STRIDE + bc4 * 4,
                           Bg + (size_t)(k0 + p * 8) * N);
            cp_commit();
        }

        // Compute stage kt
        float* Ac = smem + (kt % NSTAGE) * STAGE_FLOATS;
        float* Bc = Ac + A_STAGE;
        #pragma unroll
        for (int ks = 0; ks < BK; ks += 8) {
            wmma::fragment<wmma::matrix_a, 16, 16, 8, wmma::precision::tf32, wmma::row_major> af[4];
            wmma::fragment<wmma::matrix_b, 16, 16, 8, wmma::precision::tf32, wmma::row_major> bf[2];
            #pragma unroll
            for (int i = 0; i < 4; i++)
                wmma::load_matrix_sync(af[i], Ac + (wy * 64 + i * 16) * A_STRIDE + ks, A_STRIDE);
            #pragma unroll
            for (int j = 0; j < 2; j++)
                wmma::load_matrix_sync(bf[j], Bc + ks * B_STRIDE + wx * 32 + j * 16, B_STRIDE);
            #pragma unroll
            for (int i = 0; i < 4; i++)
                #pragma unroll
                for (int j = 0; j < 2; j++)
                    wmma::mma_sync(acc[i][j], af[i], bf[j], acc[i][j]);
        }
    }

    if (bias == nullptr) {
        #pragma unroll
        for (int i = 0; i < 4; i++)
            #pragma unroll
            for (int j = 0; j < 2; j++) {
                int r0 = tileM * BM + wy * 64 + i * 16;
                int c0 = tileN * BN + wx * 32 + j * 16;
                wmma::store_matrix_sync(Co + (size_t)r0 * N + c0, acc[i][j], N,
                                        wmma::mem_row_major);
            }
    } else {
        __syncthreads();   // safe to reuse pipeline smem for epilogue staging
        float* epi = smem + warp * 256;
        const int er = lane >> 1;            // row 0..15
        const int ec = (lane & 1) * 8;       // col 0 or 8
        #pragma unroll
        for (int i = 0; i < 4; i++)
            #pragma unroll
            for (int j = 0; j < 2; j++) {
                wmma::store_matrix_sync(epi, acc[i][j], 16, wmma::mem_row_major);
                __syncwarp();
                int gr = tileM * BM + wy * 64 + i * 16 + er;
                int gc = tileN * BN + wx * 32 + j * 16 + ec;
                float4 v0 = *(float4*)(epi + er * 16 + ec);
                float4 v1 = *(float4*)(epi + er * 16 + ec + 4);
                float4 b0 = __ldg((const float4*)(bias + gc));
                float4 b1 = __ldg((const float4*)(bias + gc + 4));
                v0.x += b0.x; v0.y += b0.y; v0.z += b0.z; v0.w += b0.w;
                v1.x += b1.x; v1.y += b1.y; v1.z += b1.z; v1.w += b1.w;
                *(float4*)(Co + (size_t)gr * N + gc)     = v0;
                *(float4*)(Co + (size_t)gr * N + gc + 4) = v1;
                __syncwarp();
            }
    }
}

// ---------------------------------------------------------------------------
// Dilated local attention (K=3 taps, dilations 1,2,3), mean over 3 branches.
// One warp per token; lane owns 8 channels. Reads g_qkv (merged layout:
// token-major, 2304 floats/token), writes g_comb (tf32-rounded).
// Reference zero-pads: out-of-range taps contribute logit 0 and value 0.
// ---------------------------------------------------------------------------
__global__ __launch_bounds__(256) void attn_kernel()
{
    const int lane = threadIdx.x & 31;
    const int t    = blockIdx.x * 8 + (threadIdx.x >> 5);   // token
    const int n    = t & (SEQ - 1);                         // pos within batch
    const float scale = 0.0625f;                            // 256^-0.5

    float out[8];
    #pragma unroll
    for (int c = 0; c < 8; c++) out[c] = 0.0f;

    const float* tok = g_qkv + (size_t)t * N_ALL;

    #pragma unroll
    for (int br = 0; br < 3; br++) {
        const int d = br + 1;
        const float* base = tok + br * N_QKV;

        float q[8];
        {
            float4 a = *(const float4*)(base + lane * 8);
            float4 b = *(const float4*)(base + lane * 8 + 4);
            q[0]=a.x; q[1]=a.y; q[2]=a.z; q[3]=a.w;
            q[4]=b.x; q[5]=b.y; q[6]=b.z; q[7]=b.w;
        }

        float lg[3];
        float vv[3][8];
        #pragma unroll
        for (int j = 0; j < 3; j++) {
            int off = (j - 1) * d;
            bool ok = ((unsigned)(n + off) < (unsigned)SEQ);
            float dot = 0.0f;
            if (ok) {
                const float* kr = base + (ptrdiff_t)off * N_ALL + C_DIM;
                float4 k0 = *(const float4*)(kr + lane * 8);
                float4 k1 = *(const float4*)(kr + lane * 8 + 4);
                dot = q[0]*k0.x + q[1]*k0.y + q[2]*k0.z + q[3]*k0.w
                    + q[4]*k1.x + q[5]*k1.y + q[6]*k1.z + q[7]*k1.w;
                const float* vr = base + (ptrdiff_t)off * N_ALL + 2 * C_DIM;
                float4 v0 = *(const float4*)(vr + lane * 8);
                float4 v1 = *(const float4*)(vr + lane * 8 + 4);
                vv[j][0]=v0.x; vv[j][1]=v0.y; vv[j][2]=v0.z; vv[j][3]=v0.w;
                vv[j][4]=v1.x; vv[j][5]=v1.y; vv[j][6]=v1.z; vv[j][7]=v1.w;
            } else {
                #pragma unroll
                for (int c = 0; c < 8; c++) vv[j][c] = 0.0f;
            }
            lg[j] = dot;   // 0 when out-of-range (zero-padded k row)
        }

        // Warp-reduce the three partial dot products
        #pragma unroll
        for (int s = 16; s > 0; s >>= 1) {
            lg[0] += __shfl_xor_sync(0xffffffffu, lg[0], s);
            lg[1] += __shfl_xor_sync(0xffffffffu, lg[1], s);
            lg[2] += __shfl_xor_sync(0xffffffffu, lg[2], s);
        }
        lg[0] *= scale; lg[1] *= scale; lg[2] *= scale;

        float m  = fmaxf(lg[0], fmaxf(lg[1], lg[2]));
        float e0 = expf(lg[0] - m);
        float e1 = expf(lg[1] - m);
        float e2 = expf(lg[2] - m);
        float inv = 1.0f / (e0 + e1 + e2);
        float a0 = e0 * inv, a1 = e1 * inv, a2 = e2 * inv;

        #pragma unroll
        for (int c = 0; c < 8; c++)
            out[c] += a0 * vv[0][c] + a1 * vv[1][c] + a2 * vv[2][c];
    }

    const float third = 1.0f / 3.0f;
    float4 o0, o1;
    o0.x = to_tf32(out[0]*third); o0.y = to_tf32(out[1]*third);
    o0.z = to_tf32(out[2]*third); o0.w = to_tf32(out[3]*third);
    o1.x = to_tf32(out[4]*third); o1.y = to_tf32(out[5]*third);
    o1.z = to_tf32(out[6]*third); o1.w = to_tf32(out[7]*third);
    float* dst = g_comb + (size_t)t * C_DIM + lane * 8;
    *(float4*)(dst)     = o0;
    *(float4*)(dst + 4) = o1;
}

// ---------------------------------------------------------------------------
// kernel_launch
// Inputs: d_in[0]=x (16,4096,256) f32, d_in[1]=Wqkv (3,256,768) f32,
//         d_in[2]=Wproj (256,256) f32, d_in[3]=bproj (256,) f32
// Output: (16,4096,256) f32
// ---------------------------------------------------------------------------
extern "C" void kernel_launch(void* const* d_in, const int* in_sizes, int n_in,
                              void* d_out, int out_size)
{
    const float* x     = (const float*)d_in[0];
    const float* Wqkv  = (const float*)d_in[1];
    const float* Wproj = (const float*)d_in[2];
    const float* bproj = (const float*)d_in[3];
    float*       out   = (float*)d_out;

    float *qkv, *comb, *x32, *wq32, *wp32;
    cudaGetSymbolAddress((void**)&qkv,  g_qkv);
    cudaGetSymbolAddress((void**)&comb, g_comb);
    cudaGetSymbolAddress((void**)&x32,  g_x32);
    cudaGetSymbolAddress((void**)&wq32, g_wq32);
    cudaGetSymbolAddress((void**)&wp32, g_wp32);

    static bool attr_done = false;
    if (!attr_done) {
        cudaFuncSetAttribute(gemm_tf32_async,
                             cudaFuncAttributeMaxDynamicSharedMemorySize,
                             SMEM_FLOATS * sizeof(float));
        attr_done = true;
    }

    // 0) Round inputs to tf32 once; repack Wqkv into merged-N layout
    round_tf32<<<2048, 256>>>((const float4*)x, (float4*)x32,
                              (size_t)TOKENS * C_DIM / 4);
    repack_wqkv<<<576, 256>>>((const float4*)Wqkv, (float4*)wq32);
    round_tf32<<<16, 256>>>((const float4*)Wproj, (float4*)wp32,
                            (size_t)C_DIM * C_DIM / 4);

    // 1) Merged QKV GEMM: (65536x256) @ (256x2304)
    {
        dim3 grid(N_ALL / BN, TOKENS / BM, 1);
        gemm_tf32_async<<<grid, 256, SMEM_FLOATS * sizeof(float)>>>(
            x32, wq32, qkv, TOKENS, N_ALL, C_DIM, nullptr);
    }

    // 2) Fused dilated local attention + mean over branches
    attn_kernel<<<TOKENS / 8, 256>>>();

    // 3) Proj GEMM with fused bias: (65536x256) @ (256x256) + b -> out
    {
        dim3 grid(C_DIM / BN, TOKENS / BM, 1);
        gemm_tf32_async<<<grid, 256, SMEM_FLOATS * sizeof(float)>>>(
            comb, wp32, out, TOKENS, C_DIM, C_DIM, bproj);
    }
}